// round 5
// baseline (speedup 1.0000x reference)
#include <cuda_runtime.h>
#include <math.h>
#include <stdint.h>

// ---------------- capacities (match problem shapes) ----------------
#define NMAX 100096      // 100000 nodes, padded
#define EMAX 1600000
#define BMAX 16384
#define FDIM 128
#define HDIM 128

// ---------------- device scratch (no allocs allowed) ----------------
__device__ float d_mean0[(size_t)NMAX * FDIM];   // layer0 neighbor mean, later unused
__device__ float d_h   [(size_t)NMAX * HDIM];    // layer0 output
__device__ float d_aggU[(size_t)BMAX * HDIM];    // layer1 neighbor mean (user rows only)
__device__ float d_ue  [(size_t)BMAX * HDIM];    // clipped user embeddings
__device__ float d_gate[(size_t)BMAX * 512];     // LSTM gates
__device__ float d_lstm[(size_t)BMAX * HDIM];    // LSTM output
__device__ float d_z0  [(size_t)BMAX * HDIM];
__device__ float d_z1  [(size_t)BMAX * 64];
__device__ int   d_count [NMAX];
__device__ int   d_rowptr[NMAX];
__device__ int   d_cursor[NMAX];
__device__ int   d_srcs  [EMAX];
__device__ int   d_bsum  [1024];

__device__ __forceinline__ float clamp10(float v) {
    return fminf(10.0f, fmaxf(-10.0f, v));
}

// ---------------- CSR build ----------------
__global__ void k_zero(int n) {
    int i = blockIdx.x * blockDim.x + threadIdx.x;
    if (i < n) { d_count[i] = 0; d_cursor[i] = 0; }
}

__global__ void k_count(const int* __restrict__ dst, int E) {
    int e = blockIdx.x * blockDim.x + threadIdx.x;
    if (e < E) atomicAdd(&d_count[dst[e]], 1);
}

__global__ void k_scan1(int n) {
    __shared__ int sh[1024];
    int i = blockIdx.x * 1024 + threadIdx.x;
    int v = (i < n) ? d_count[i] : 0;
    sh[threadIdx.x] = v;
    __syncthreads();
    for (int off = 1; off < 1024; off <<= 1) {
        int t = (threadIdx.x >= off) ? sh[threadIdx.x - off] : 0;
        __syncthreads();
        sh[threadIdx.x] += t;
        __syncthreads();
    }
    if (i < n) d_rowptr[i] = sh[threadIdx.x] - v;   // exclusive
    if (threadIdx.x == 1023) d_bsum[blockIdx.x] = sh[1023];
}

__global__ void k_scan2(int nb) {
    __shared__ int sh[1024];
    int v = (threadIdx.x < nb) ? d_bsum[threadIdx.x] : 0;
    sh[threadIdx.x] = v;
    __syncthreads();
    for (int off = 1; off < 1024; off <<= 1) {
        int t = (threadIdx.x >= off) ? sh[threadIdx.x - off] : 0;
        __syncthreads();
        sh[threadIdx.x] += t;
        __syncthreads();
    }
    if (threadIdx.x < nb) d_bsum[threadIdx.x] = sh[threadIdx.x] - v;  // exclusive
}

__global__ void k_scan3(int n) {
    int i = blockIdx.x * blockDim.x + threadIdx.x;
    if (i < n) d_rowptr[i] += d_bsum[i >> 10];
}

__global__ void k_scatter(const int* __restrict__ src, const int* __restrict__ dst, int E) {
    int e = blockIdx.x * blockDim.x + threadIdx.x;
    if (e < E) {
        int d = dst[e];
        int pos = atomicAdd(&d_cursor[d], 1);
        d_srcs[d_rowptr[d] + pos] = src[e];
    }
}

// ---------------- mean aggregation: one warp per output row ----------------
// out[w] = mean_{s in N(node)} X[s], node = gath ? gath[w] : w
__global__ void k_agg(const float* __restrict__ X, const int* __restrict__ gath,
                      float* __restrict__ out, int nrows) {
    int w = (blockIdx.x * blockDim.x + threadIdx.x) >> 5;
    int lane = threadIdx.x & 31;
    if (w >= nrows) return;
    int node = gath ? gath[w] : w;
    int start = d_rowptr[node];
    int cnt   = d_count[node];
    float4 acc = make_float4(0.f, 0.f, 0.f, 0.f);
    for (int j = 0; j < cnt; j++) {
        int s = d_srcs[start + j];
        float4 v = *reinterpret_cast<const float4*>(X + (size_t)s * 128 + (lane << 2));
        acc.x += v.x; acc.y += v.y; acc.z += v.z; acc.w += v.w;
    }
    float inv = 1.0f / fmaxf((float)cnt, 1.0f);
    acc.x *= inv; acc.y *= inv; acc.z *= inv; acc.w *= inv;
    *reinterpret_cast<float4*>(out + (size_t)w * 128 + (lane << 2)) = acc;
}

// ---------------- generic fused SGEMM ----------------
// C[M, Nout] = act( [A0 | A1(gathered,clipped)] @ [W0 | W1]^T + bias1 + bias2 + roleW[:, roleOff + roles[row]] )
// A0: [M, K0] stride K0.  A1 rows: g1 ? g1[row] : row, stride K1.
// W0: [Nout, K0] stride ldw0 (k < K0).  W1: [Nout, K1] stride ldw1 (k >= K0).
// act: 0 none, 1 relu, 2 clip(+-10)
__global__ __launch_bounds__(256, 2)
void k_sgemm(const float* __restrict__ A0, const float* __restrict__ A1,
             const int* __restrict__ g1, int clip1, int K0, int K1,
             const float* __restrict__ W0, int ldw0,
             const float* __restrict__ W1, int ldw1,
             const float* __restrict__ bias1, const float* __restrict__ bias2,
             const float* __restrict__ roleW, int roleLd, int roleOff,
             const int* __restrict__ roles,
             float* __restrict__ C, int ldc, int M, int Nout, int act) {
    __shared__ float As[16][128];
    __shared__ float Bs[16][128];
    const int tid = threadIdx.x;
    const int tx = tid & 15, ty = tid >> 4;
    const int rowBase = blockIdx.y * 128;
    const int colBase = blockIdx.x * 128;
    const int K = K0 + K1;

    float acc[8][8];
#pragma unroll
    for (int i = 0; i < 8; i++)
#pragma unroll
        for (int j = 0; j < 8; j++) acc[i][j] = 0.f;

    for (int kt = 0; kt < K; kt += 16) {
        // load A tile (128 rows x 16 k) as float4 per thread x2, transpose into As[k][m]
#pragma unroll
        for (int it = 0; it < 2; it++) {
            int idx = tid + it * 256;       // 0..511
            int m = idx >> 2;               // 0..127
            int kq = (idx & 3) << 2;        // 0,4,8,12
            int row = rowBase + m;
            float4 v = make_float4(0.f, 0.f, 0.f, 0.f);
            if (row < M) {
                int kg = kt + kq;
                if (kg < K0) {
                    v = *reinterpret_cast<const float4*>(A0 + (size_t)row * K0 + kg);
                } else {
                    int r1 = g1 ? g1[row] : row;
                    v = *reinterpret_cast<const float4*>(A1 + (size_t)r1 * K1 + (kg - K0));
                    if (clip1) {
                        v.x = clamp10(v.x); v.y = clamp10(v.y);
                        v.z = clamp10(v.z); v.w = clamp10(v.w);
                    }
                }
            }
            As[kq + 0][m] = v.x; As[kq + 1][m] = v.y;
            As[kq + 2][m] = v.z; As[kq + 3][m] = v.w;
        }
        // load W tile (128 n x 16 k), scalar loads (w_ih stride 261 is not 16B aligned)
#pragma unroll
        for (int it = 0; it < 8; it++) {
            int idx = tid + it * 256;       // 0..2047
            int n = idx >> 4;               // 0..127
            int kk = idx & 15;
            int ng = colBase + n;
            float wv = 0.f;
            if (ng < Nout) {
                int kg = kt + kk;
                wv = (kg < K0) ? W0[(size_t)ng * ldw0 + kg]
                               : W1[(size_t)ng * ldw1 + (kg - K0)];
            }
            Bs[kk][n] = wv;
        }
        __syncthreads();
#pragma unroll
        for (int kk = 0; kk < 16; kk++) {
            float a[8], b[8];
#pragma unroll
            for (int i = 0; i < 8; i++) a[i] = As[kk][ty * 8 + i];
#pragma unroll
            for (int j = 0; j < 8; j++) b[j] = Bs[kk][tx * 8 + j];
#pragma unroll
            for (int i = 0; i < 8; i++)
#pragma unroll
                for (int j = 0; j < 8; j++) acc[i][j] += a[i] * b[j];
        }
        __syncthreads();
    }

    // epilogue
#pragma unroll
    for (int i = 0; i < 8; i++) {
        int row = rowBase + ty * 8 + i;
        if (row >= M) continue;
        int rl = roleW ? roles[row] : 0;
#pragma unroll
        for (int j = 0; j < 8; j++) {
            int n = colBase + tx * 8 + j;
            if (n >= Nout) continue;
            float v = acc[i][j];
            if (bias1) v += bias1[n];
            if (bias2) v += bias2[n];
            if (roleW) v += roleW[(size_t)n * roleLd + roleOff + rl];
            if (act == 1) v = fmaxf(v, 0.f);
            else if (act == 2) v = clamp10(v);
            C[(size_t)row * ldc + n] = v;
        }
    }
}

// ---------------- LSTM pointwise (h0=c0=0: c = sig(i)*tanh(g); out = clip(sig(o)*tanh(c))) ----------------
__global__ void k_lstm(int B) {
    int idx = blockIdx.x * blockDim.x + threadIdx.x;
    if (idx >= B * 128) return;
    int b = idx >> 7, j = idx & 127;
    const float* g = d_gate + (size_t)b * 512;
    float i_ = g[j];           // gate i
    float gg = g[256 + j];     // gate g
    float o_ = g[384 + j];     // gate o
    float si = 1.0f / (1.0f + expf(-i_));
    float so = 1.0f / (1.0f + expf(-o_));
    float c = si * tanhf(gg);
    d_lstm[idx] = clamp10(so * tanhf(c));
}

// ---------------- final tiny layer: out[B,5] = z1[B,64] @ wc2[5,64]^T + bc2 ----------------
__global__ void k_out(const float* __restrict__ wc2, const float* __restrict__ bc2,
                      float* __restrict__ out, int B) {
    __shared__ float w[320];
    __shared__ float bb[5];
    int tid = threadIdx.x;
    if (tid < 320) w[tid] = wc2[tid];
    if (tid < 5)   bb[tid] = bc2[tid];
    __syncthreads();
    int b = blockIdx.x * blockDim.x + tid;
    if (b >= B) return;
    const float* z = d_z1 + (size_t)b * 64;
    float a0 = bb[0], a1 = bb[1], a2 = bb[2], a3 = bb[3], a4 = bb[4];
#pragma unroll
    for (int k = 0; k < 64; k++) {
        float zv = z[k];
        a0 += zv * w[k];
        a1 += zv * w[64 + k];
        a2 += zv * w[128 + k];
        a3 += zv * w[192 + k];
        a4 += zv * w[256 + k];
    }
    float* o = out + (size_t)b * 5;
    o[0] = a0; o[1] = a1; o[2] = a2; o[3] = a3; o[4] = a4;
}

// ---------------- launch ----------------
extern "C" void kernel_launch(void* const* d_in, const int* in_sizes, int n_in,
                              void* d_out, int out_size) {
    const float* x     = (const float*)d_in[0];
    const int*   edge  = (const int*)  d_in[1];
    const int*   uid   = (const int*)  d_in[2];
    const int*   roles = (const int*)  d_in[3];
    const float* w_l0  = (const float*)d_in[4];
    const float* b_l0  = (const float*)d_in[5];
    const float* w_r0  = (const float*)d_in[6];
    const float* w_l1  = (const float*)d_in[7];
    const float* b_l1  = (const float*)d_in[8];
    const float* w_r1  = (const float*)d_in[9];
    const float* w_ih  = (const float*)d_in[10];
    /* w_hh = d_in[11] unused: h0 = 0 */
    const float* b_ih  = (const float*)d_in[12];
    const float* b_hh  = (const float*)d_in[13];
    const float* wc0   = (const float*)d_in[14];
    const float* bc0   = (const float*)d_in[15];
    const float* wc1   = (const float*)d_in[16];
    const float* bc1   = (const float*)d_in[17];
    const float* wc2   = (const float*)d_in[18];
    const float* bc2   = (const float*)d_in[19];
    float* out = (float*)d_out;

    const int N = in_sizes[0] / FDIM;
    const int E = in_sizes[1] / 2;
    const int B = in_sizes[2];
    const int* src = edge;
    const int* dst = edge + E;

    float *mean0, *hbuf, *aggU, *ue, *gate, *lstm, *z0, *z1;
    cudaGetSymbolAddress((void**)&mean0, d_mean0);
    cudaGetSymbolAddress((void**)&hbuf,  d_h);
    cudaGetSymbolAddress((void**)&aggU,  d_aggU);
    cudaGetSymbolAddress((void**)&ue,    d_ue);
    cudaGetSymbolAddress((void**)&gate,  d_gate);
    cudaGetSymbolAddress((void**)&lstm,  d_lstm);
    cudaGetSymbolAddress((void**)&z0,    d_z0);
    cudaGetSymbolAddress((void**)&z1,    d_z1);

    // --- CSR build (shared by both SAGE layers) ---
    k_zero<<<(N + 255) / 256, 256>>>(N);
    k_count<<<(E + 255) / 256, 256>>>(dst, E);
    int nb = (N + 1023) / 1024;
    k_scan1<<<nb, 1024>>>(N);
    k_scan2<<<1, 1024>>>(nb);
    k_scan3<<<(N + 255) / 256, 256>>>(N);
    k_scatter<<<(E + 255) / 256, 256>>>(src, dst, E);

    // --- layer 0: mean over neighbors of x, then h = relu([mean|x] @ [w_l0|w_r0]^T + b_l0) ---
    k_agg<<<(N + 7) / 8, 256>>>(x, nullptr, mean0, N);
    {
        dim3 g((HDIM + 127) / 128, (N + 127) / 128);
        k_sgemm<<<g, 256>>>(mean0, x, nullptr, 0, 128, 128,
                            w_l0, 128, w_r0, 128,
                            b_l0, nullptr,
                            nullptr, 0, 0, nullptr,
                            hbuf, 128, N, HDIM, /*relu*/1);
    }

    // --- layer 1 restricted to user rows: aggU[b] = mean over N(uid[b]) of h ---
    k_agg<<<(B + 7) / 8, 256>>>(hbuf, uid, aggU, B);
    {   // ue = clip([aggU | h[uid]] @ [w_l1|w_r1]^T + b_l1)
        dim3 g(1, (B + 127) / 128);
        k_sgemm<<<g, 256>>>(aggU, hbuf, uid, 0, 128, 128,
                            w_l1, 128, w_r1, 128,
                            b_l1, nullptr,
                            nullptr, 0, 0, nullptr,
                            ue, 128, B, HDIM, /*clip*/2);
    }

    // --- gates = [ue | clip(x[uid])] @ w_ih[:, :256]^T + w_ih[:, 256+role] + b_ih + b_hh ---
    {
        dim3 g(4, (B + 127) / 128);
        k_sgemm<<<g, 256>>>(ue, x, uid, /*clip uf*/1, 128, 128,
                            w_ih, 261, w_ih + 128, 261,
                            b_ih, b_hh,
                            w_ih, 261, 256, roles,
                            gate, 512, B, 512, /*none*/0);
    }
    k_lstm<<<(B * 128 + 255) / 256, 256>>>(B);

    // --- classifier head ---
    {   // z0 = relu([ue | lstm] @ wc0^T + bc0)
        dim3 g(1, (B + 127) / 128);
        k_sgemm<<<g, 256>>>(ue, lstm, nullptr, 0, 128, 128,
                            wc0, 256, wc0 + 128, 256,
                            bc0, nullptr,
                            nullptr, 0, 0, nullptr,
                            z0, 128, B, 128, 1);
    }
    {   // z1 = relu(z0 @ wc1^T + bc1)   (Nout = 64)
        dim3 g(1, (B + 127) / 128);
        k_sgemm<<<g, 256>>>(z0, nullptr, nullptr, 0, 128, 0,
                            wc1, 128, nullptr, 0,
                            bc1, nullptr,
                            nullptr, 0, 0, nullptr,
                            z1, 64, B, 64, 1);
    }
    k_out<<<(B + 511) / 512, 512>>>(wc2, bc2, out, B);
}

// round 6
// speedup vs baseline: 1.3750x; 1.3750x over previous
#include <cuda_runtime.h>
#include <math.h>
#include <stdint.h>

// ---------------- capacities ----------------
#define NMAX 100096
#define EMAX 1600000
#define BMAX 16384
#define FDIM 128
#define HDIM 128

// ---------------- device scratch ----------------
__device__ float d_mean0[(size_t)NMAX * FDIM];
__device__ float d_h   [(size_t)NMAX * HDIM];
__device__ float d_aggU[(size_t)BMAX * HDIM];
__device__ float d_ue  [(size_t)BMAX * HDIM];
__device__ float d_gate[(size_t)BMAX * 512];
__device__ float d_lstm[(size_t)BMAX * HDIM];
__device__ float d_z0  [(size_t)BMAX * HDIM];
__device__ float d_z1  [(size_t)BMAX * 64];
__device__ int   d_count [NMAX];
__device__ int   d_rowptr[NMAX];
__device__ int   d_cursor[NMAX];
__device__ int   d_srcs  [EMAX];
__device__ int   d_bsum  [1024];

__device__ __forceinline__ float clamp10(float v) {
    return fminf(10.0f, fmaxf(-10.0f, v));
}

// 3xTF32 split: hi = top-10 mantissa (truncated), lo = exact fp32 residual.
// HMMA consumes only the tf32 field of each b32 reg, so lo needs no cvt.
__device__ __forceinline__ void tf32split(float a, unsigned &hi, unsigned &lo) {
    unsigned u = __float_as_uint(a);
    hi = u & 0xffffe000u;
    lo = __float_as_uint(a - __uint_as_float(hi));
}

__device__ __forceinline__ void mma_tf32(float* c,
        unsigned a0, unsigned a1, unsigned a2, unsigned a3,
        unsigned b0, unsigned b1) {
    asm volatile(
        "mma.sync.aligned.m16n8k8.row.col.f32.tf32.tf32.f32 "
        "{%0,%1,%2,%3}, {%4,%5,%6,%7}, {%8,%9}, {%0,%1,%2,%3};"
        : "+f"(c[0]), "+f"(c[1]), "+f"(c[2]), "+f"(c[3])
        : "r"(a0), "r"(a1), "r"(a2), "r"(a3), "r"(b0), "r"(b1));
}

// ---------------- CSR build ----------------
__global__ void k_zero(int n) {
    int i = blockIdx.x * blockDim.x + threadIdx.x;
    if (i < n) { d_count[i] = 0; d_cursor[i] = 0; }
}

__global__ void k_count(const int* __restrict__ dst, int E) {
    int e = blockIdx.x * blockDim.x + threadIdx.x;
    if (e < E) atomicAdd(&d_count[dst[e]], 1);
}

__global__ void k_scan1(int n) {
    __shared__ int sh[1024];
    int i = blockIdx.x * 1024 + threadIdx.x;
    int v = (i < n) ? d_count[i] : 0;
    sh[threadIdx.x] = v;
    __syncthreads();
    for (int off = 1; off < 1024; off <<= 1) {
        int t = (threadIdx.x >= off) ? sh[threadIdx.x - off] : 0;
        __syncthreads();
        sh[threadIdx.x] += t;
        __syncthreads();
    }
    if (i < n) d_rowptr[i] = sh[threadIdx.x] - v;
    if (threadIdx.x == 1023) d_bsum[blockIdx.x] = sh[1023];
}

__global__ void k_scan2(int nb) {
    __shared__ int sh[1024];
    int v = (threadIdx.x < nb) ? d_bsum[threadIdx.x] : 0;
    sh[threadIdx.x] = v;
    __syncthreads();
    for (int off = 1; off < 1024; off <<= 1) {
        int t = (threadIdx.x >= off) ? sh[threadIdx.x - off] : 0;
        __syncthreads();
        sh[threadIdx.x] += t;
        __syncthreads();
    }
    if (threadIdx.x < nb) d_bsum[threadIdx.x] = sh[threadIdx.x] - v;
}

__global__ void k_scan3(int n) {
    int i = blockIdx.x * blockDim.x + threadIdx.x;
    if (i < n) d_rowptr[i] += d_bsum[i >> 10];
}

__global__ void k_scatter(const int* __restrict__ src, const int* __restrict__ dst, int E) {
    int e = blockIdx.x * blockDim.x + threadIdx.x;
    if (e < E) {
        int d = dst[e];
        int pos = atomicAdd(&d_cursor[d], 1);
        d_srcs[d_rowptr[d] + pos] = src[e];
    }
}

// ---------------- mean aggregation: one warp per row, 2-way MLP unroll ----------------
__global__ void k_agg(const float* __restrict__ X, const int* __restrict__ gath,
                      float* __restrict__ out, int nrows) {
    int w = (blockIdx.x * blockDim.x + threadIdx.x) >> 5;
    int lane = threadIdx.x & 31;
    if (w >= nrows) return;
    int node = gath ? gath[w] : w;
    int start = d_rowptr[node];
    int cnt   = d_count[node];
    const float* base = X + (lane << 2);
    float4 acc = make_float4(0.f, 0.f, 0.f, 0.f);
    int j = 0;
    for (; j + 1 < cnt; j += 2) {
        int s0 = d_srcs[start + j];
        int s1 = d_srcs[start + j + 1];
        float4 v0 = *reinterpret_cast<const float4*>(base + (size_t)s0 * 128);
        float4 v1 = *reinterpret_cast<const float4*>(base + (size_t)s1 * 128);
        acc.x += v0.x + v1.x; acc.y += v0.y + v1.y;
        acc.z += v0.z + v1.z; acc.w += v0.w + v1.w;
    }
    if (j < cnt) {
        int s0 = d_srcs[start + j];
        float4 v0 = *reinterpret_cast<const float4*>(base + (size_t)s0 * 128);
        acc.x += v0.x; acc.y += v0.y; acc.z += v0.z; acc.w += v0.w;
    }
    float inv = 1.0f / fmaxf((float)cnt, 1.0f);
    acc.x *= inv; acc.y *= inv; acc.z *= inv; acc.w *= inv;
    *reinterpret_cast<float4*>(out + (size_t)w * 128 + (lane << 2)) = acc;
}

// ---------------- fused 3xTF32 tensor-core GEMM ----------------
// C[M,Nout] = act( [A0 | A1(gathered,clipped)] @ [W0 | W1]^T
//                  + bias1 + bias2 + roleW[:, roleOff + roles[row]] )
// Tile: BM=128, BN=64, BK=16.  colBase = bx*64 (+colSkip for bx>=2, to skip dead cols).
__global__ __launch_bounds__(256, 2)
void k_mma(const float* __restrict__ A0, const float* __restrict__ A1,
           const int* __restrict__ g1, int clip1, int K0, int K1,
           const float* __restrict__ W0, int ldw0,
           const float* __restrict__ W1, int ldw1, int wvec,
           const float* __restrict__ bias1, const float* __restrict__ bias2,
           const float* __restrict__ roleW, int roleLd, int roleOff,
           const int* __restrict__ roles,
           float* __restrict__ C, int ldc, int M, int Nout, int act, int colSkip) {
    // interleaved (hi,lo) pairs; stride 36 words keeps fragment LDS near conflict-free
    __shared__ unsigned As2[128][36];
    __shared__ unsigned Bs2[64][36];
    const int tid = threadIdx.x;
    const int lane = tid & 31;
    const int wid = tid >> 5;
    const int warp_m = wid & 3;   // 4 x 32 rows
    const int warp_n = wid >> 2;  // 2 x 32 cols
    const int rowBase = blockIdx.y * 128;
    int colBase = blockIdx.x * 64;
    if (blockIdx.x >= 2) colBase += colSkip;
    const int K = K0 + K1;
    const int ar = lane >> 2, ac = lane & 3;

    float acc[2][4][4];
#pragma unroll
    for (int i = 0; i < 2; i++)
#pragma unroll
        for (int j = 0; j < 4; j++)
#pragma unroll
            for (int k = 0; k < 4; k++) acc[i][j][k] = 0.f;

    for (int kt = 0; kt < K; kt += 16) {
        // ---- A tile: 128 x 16 floats, 2 float4 per thread ----
#pragma unroll
        for (int it = 0; it < 2; it++) {
            int idx = tid + it * 256;        // 0..511
            int m = idx >> 2;                // 0..127
            int kq = (idx & 3) << 2;         // 0,4,8,12
            int row = rowBase + m;
            float4 v = make_float4(0.f, 0.f, 0.f, 0.f);
            if (row < M) {
                int kg = kt + kq;
                if (kg < K0) {
                    v = *reinterpret_cast<const float4*>(A0 + (size_t)row * K0 + kg);
                } else {
                    int r1 = g1 ? g1[row] : row;
                    v = *reinterpret_cast<const float4*>(A1 + (size_t)r1 * K1 + (kg - K0));
                    if (clip1) {
                        v.x = clamp10(v.x); v.y = clamp10(v.y);
                        v.z = clamp10(v.z); v.w = clamp10(v.w);
                    }
                }
            }
            unsigned h0,l0,h1,l1,h2,l2,h3,l3;
            tf32split(v.x, h0, l0); tf32split(v.y, h1, l1);
            tf32split(v.z, h2, l2); tf32split(v.w, h3, l3);
            unsigned* p = &As2[m][kq << 1];
            reinterpret_cast<uint4*>(p)[0] = make_uint4(h0, l0, h1, l1);
            reinterpret_cast<uint4*>(p)[1] = make_uint4(h2, l2, h3, l3);
        }
        // ---- B tile: 64 x 16 floats (W row-major [Nout][K]) ----
        if (wvec) {
            int n = tid >> 2;                // 0..63
            int kq = (tid & 3) << 2;
            int ng = colBase + n;
            float4 v = make_float4(0.f, 0.f, 0.f, 0.f);
            if (ng < Nout) {
                int kg = kt + kq;
                v = (kg < K0) ? *reinterpret_cast<const float4*>(W0 + (size_t)ng * ldw0 + kg)
                              : *reinterpret_cast<const float4*>(W1 + (size_t)ng * ldw1 + (kg - K0));
            }
            unsigned h0,l0,h1,l1,h2,l2,h3,l3;
            tf32split(v.x, h0, l0); tf32split(v.y, h1, l1);
            tf32split(v.z, h2, l2); tf32split(v.w, h3, l3);
            unsigned* p = &Bs2[n][kq << 1];
            reinterpret_cast<uint4*>(p)[0] = make_uint4(h0, l0, h1, l1);
            reinterpret_cast<uint4*>(p)[1] = make_uint4(h2, l2, h3, l3);
        } else {  // scalar path (w_ih row stride 261: not 16B aligned)
#pragma unroll
            for (int it = 0; it < 4; it++) {
                int idx = tid + it * 256;    // 0..1023
                int n = idx >> 4;            // 0..63
                int kk = idx & 15;
                int ng = colBase + n;
                float wv = 0.f;
                if (ng < Nout) {
                    int kg = kt + kk;
                    wv = (kg < K0) ? W0[(size_t)ng * ldw0 + kg]
                                   : W1[(size_t)ng * ldw1 + (kg - K0)];
                }
                unsigned h, l; tf32split(wv, h, l);
                Bs2[n][2 * kk]     = h;
                Bs2[n][2 * kk + 1] = l;
            }
        }
        __syncthreads();
        // ---- compute: 2 k8-steps ----
#pragma unroll
        for (int ks = 0; ks < 2; ks++) {
            int k0 = ks << 3;
            uint2 a[2][4];
#pragma unroll
            for (int mt = 0; mt < 2; mt++) {
                int r = warp_m * 32 + mt * 16 + ar;
                a[mt][0] = *reinterpret_cast<uint2*>(&As2[r    ][(k0 + ac)     << 1]);
                a[mt][1] = *reinterpret_cast<uint2*>(&As2[r + 8][(k0 + ac)     << 1]);
                a[mt][2] = *reinterpret_cast<uint2*>(&As2[r    ][(k0 + ac + 4) << 1]);
                a[mt][3] = *reinterpret_cast<uint2*>(&As2[r + 8][(k0 + ac + 4) << 1]);
            }
#pragma unroll
            for (int nb = 0; nb < 4; nb++) {
                int cn = warp_n * 32 + nb * 8 + ar;
                uint2 b0 = *reinterpret_cast<uint2*>(&Bs2[cn][(k0 + ac)     << 1]);
                uint2 b1 = *reinterpret_cast<uint2*>(&Bs2[cn][(k0 + ac + 4) << 1]);
#pragma unroll
                for (int mt = 0; mt < 2; mt++) {
                    mma_tf32(acc[mt][nb], a[mt][0].y, a[mt][1].y, a[mt][2].y, a[mt][3].y, b0.x, b1.x); // lo*hi
                    mma_tf32(acc[mt][nb], a[mt][0].x, a[mt][1].x, a[mt][2].x, a[mt][3].x, b0.y, b1.y); // hi*lo
                    mma_tf32(acc[mt][nb], a[mt][0].x, a[mt][1].x, a[mt][2].x, a[mt][3].x, b0.x, b1.x); // hi*hi
                }
            }
        }
        __syncthreads();
    }

    // ---- epilogue ----
#pragma unroll
    for (int mt = 0; mt < 2; mt++) {
        int r0 = rowBase + warp_m * 32 + mt * 16 + ar;
        int r1 = r0 + 8;
        int rl0 = 0, rl1 = 0;
        if (roleW) {
            if (r0 < M) rl0 = roles[r0];
            if (r1 < M) rl1 = roles[r1];
        }
#pragma unroll
        for (int nb = 0; nb < 4; nb++) {
            int c0 = colBase + warp_n * 32 + nb * 8 + ac * 2;
            if (c0 >= Nout) continue;
            float bs0 = 0.f, bs1 = 0.f;
            if (bias1) { bs0 += bias1[c0]; bs1 += bias1[c0 + 1]; }
            if (bias2) { bs0 += bias2[c0]; bs1 += bias2[c0 + 1]; }
            if (r0 < M) {
                float v0 = acc[mt][nb][0] + bs0;
                float v1 = acc[mt][nb][1] + bs1;
                if (roleW) {
                    v0 += roleW[(size_t)c0 * roleLd + roleOff + rl0];
                    v1 += roleW[(size_t)(c0 + 1) * roleLd + roleOff + rl0];
                }
                if (act == 1) { v0 = fmaxf(v0, 0.f); v1 = fmaxf(v1, 0.f); }
                else if (act == 2) { v0 = clamp10(v0); v1 = clamp10(v1); }
                *reinterpret_cast<float2*>(C + (size_t)r0 * ldc + c0) = make_float2(v0, v1);
            }
            if (r1 < M) {
                float v0 = acc[mt][nb][2] + bs0;
                float v1 = acc[mt][nb][3] + bs1;
                if (roleW) {
                    v0 += roleW[(size_t)c0 * roleLd + roleOff + rl1];
                    v1 += roleW[(size_t)(c0 + 1) * roleLd + roleOff + rl1];
                }
                if (act == 1) { v0 = fmaxf(v0, 0.f); v1 = fmaxf(v1, 0.f); }
                else if (act == 2) { v0 = clamp10(v0); v1 = clamp10(v1); }
                *reinterpret_cast<float2*>(C + (size_t)r1 * ldc + c0) = make_float2(v0, v1);
            }
        }
    }
}

// ---------------- LSTM pointwise (f-gate dead: c0=0) ----------------
__global__ void k_lstm(int B) {
    int idx = blockIdx.x * blockDim.x + threadIdx.x;
    if (idx >= B * 128) return;
    int b = idx >> 7, j = idx & 127;
    const float* g = d_gate + (size_t)b * 512;
    float i_ = g[j];
    float gg = g[256 + j];
    float o_ = g[384 + j];
    float si = 1.0f / (1.0f + expf(-i_));
    float so = 1.0f / (1.0f + expf(-o_));
    float c = si * tanhf(gg);
    d_lstm[idx] = clamp10(so * tanhf(c));
}

// ---------------- final tiny layer: out[B,5] = z1 @ wc2^T + bc2 ----------------
__global__ void k_out(const float* __restrict__ wc2, const float* __restrict__ bc2,
                      float* __restrict__ out, int B) {
    __shared__ float w[320];
    __shared__ float bb[5];
    int tid = threadIdx.x;
    if (tid < 320) w[tid] = wc2[tid];
    if (tid < 5)   bb[tid] = bc2[tid];
    __syncthreads();
    int b = blockIdx.x * blockDim.x + tid;
    if (b >= B) return;
    const float* z = d_z1 + (size_t)b * 64;
    float a0 = bb[0], a1 = bb[1], a2 = bb[2], a3 = bb[3], a4 = bb[4];
#pragma unroll
    for (int k = 0; k < 64; k++) {
        float zv = z[k];
        a0 += zv * w[k];
        a1 += zv * w[64 + k];
        a2 += zv * w[128 + k];
        a3 += zv * w[192 + k];
        a4 += zv * w[256 + k];
    }
    float* o = out + (size_t)b * 5;
    o[0] = a0; o[1] = a1; o[2] = a2; o[3] = a3; o[4] = a4;
}

// ---------------- launch ----------------
extern "C" void kernel_launch(void* const* d_in, const int* in_sizes, int n_in,
                              void* d_out, int out_size) {
    const float* x     = (const float*)d_in[0];
    const int*   edge  = (const int*)  d_in[1];
    const int*   uid   = (const int*)  d_in[2];
    const int*   roles = (const int*)  d_in[3];
    const float* w_l0  = (const float*)d_in[4];
    const float* b_l0  = (const float*)d_in[5];
    const float* w_r0  = (const float*)d_in[6];
    const float* w_l1  = (const float*)d_in[7];
    const float* b_l1  = (const float*)d_in[8];
    const float* w_r1  = (const float*)d_in[9];
    const float* w_ih  = (const float*)d_in[10];
    /* w_hh unused: h0 = 0 */
    const float* b_ih  = (const float*)d_in[12];
    const float* b_hh  = (const float*)d_in[13];
    const float* wc0   = (const float*)d_in[14];
    const float* bc0   = (const float*)d_in[15];
    const float* wc1   = (const float*)d_in[16];
    const float* bc1   = (const float*)d_in[17];
    const float* wc2   = (const float*)d_in[18];
    const float* bc2   = (const float*)d_in[19];
    float* out = (float*)d_out;

    const int N = in_sizes[0] / FDIM;
    const int E = in_sizes[1] / 2;
    const int B = in_sizes[2];
    const int* src = edge;
    const int* dst = edge + E;

    float *mean0, *hbuf, *aggU, *ue, *gate, *lstm, *z0, *z1;
    cudaGetSymbolAddress((void**)&mean0, d_mean0);
    cudaGetSymbolAddress((void**)&hbuf,  d_h);
    cudaGetSymbolAddress((void**)&aggU,  d_aggU);
    cudaGetSymbolAddress((void**)&ue,    d_ue);
    cudaGetSymbolAddress((void**)&gate,  d_gate);
    cudaGetSymbolAddress((void**)&lstm,  d_lstm);
    cudaGetSymbolAddress((void**)&z0,    d_z0);
    cudaGetSymbolAddress((void**)&z1,    d_z1);

    // --- CSR build ---
    k_zero<<<(N + 255) / 256, 256>>>(N);
    k_count<<<(E + 255) / 256, 256>>>(dst, E);
    int nb = (N + 1023) / 1024;
    k_scan1<<<nb, 1024>>>(N);
    k_scan2<<<1, 1024>>>(nb);
    k_scan3<<<(N + 255) / 256, 256>>>(N);
    k_scatter<<<(E + 255) / 256, 256>>>(src, dst, E);

    // --- layer 0 ---
    k_agg<<<(N + 7) / 8, 256>>>(x, nullptr, mean0, N);
    k_mma<<<dim3(2, (N + 127) / 128), 256>>>(
        mean0, x, nullptr, 0, 128, 128,
        w_l0, 128, w_r0, 128, /*wvec*/1,
        b_l0, nullptr, nullptr, 0, 0, nullptr,
        hbuf, 128, N, 128, /*relu*/1, 0);

    // --- layer 1 (user rows only) ---
    k_agg<<<(B + 7) / 8, 256>>>(hbuf, uid, aggU, B);
    k_mma<<<dim3(2, (B + 127) / 128), 256>>>(
        aggU, hbuf, uid, 0, 128, 128,
        w_l1, 128, w_r1, 128, 1,
        b_l1, nullptr, nullptr, 0, 0, nullptr,
        ue, 128, B, 128, /*clip*/2, 0);

    // --- gates (skip dead f-gate columns 128..255): blocks cover {0,64,256,320,384,448} ---
    k_mma<<<dim3(6, (B + 127) / 128), 256>>>(
        ue, x, uid, /*clip uf*/1, 128, 128,
        w_ih, 261, w_ih + 128, 261, /*wvec*/0,
        b_ih, b_hh, w_ih, 261, 256, roles,
        gate, 512, B, 512, /*none*/0, /*colSkip*/128);
    k_lstm<<<(B * 128 + 255) / 256, 256>>>(B);

    // --- classifier head ---
    k_mma<<<dim3(2, (B + 127) / 128), 256>>>(
        ue, lstm, nullptr, 0, 128, 128,
        wc0, 256, wc0 + 128, 256, 1,
        bc0, nullptr, nullptr, 0, 0, nullptr,
        z0, 128, B, 128, 1, 0);
    k_mma<<<dim3(1, (B + 127) / 128), 256>>>(
        z0, nullptr, nullptr, 0, 128, 0,
        wc1, 128, nullptr, 0, 1,
        bc1, nullptr, nullptr, 0, 0, nullptr,
        z1, 64, B, 64, 1, 0);
    k_out<<<(B + 511) / 512, 512>>>(wc2, bc2, out, B);
}

// round 7
// speedup vs baseline: 1.9201x; 1.3964x over previous
#include <cuda_runtime.h>
#include <cuda_bf16.h>
#include <math.h>
#include <stdint.h>

// ---------------- capacities ----------------
#define NMAX 100096
#define EMAX 1600000
#define BMAX 16384
#define FDIM 128
#define HDIM 128

// ---------------- device scratch ----------------
__device__ float d_mean0[(size_t)NMAX * FDIM];
__device__ float d_h   [(size_t)NMAX * HDIM];
__device__ float d_aggU[(size_t)BMAX * HDIM];
__device__ float d_ue  [(size_t)BMAX * HDIM];
__device__ float d_gate[(size_t)BMAX * 512];
__device__ float d_lstm[(size_t)BMAX * HDIM];
__device__ float d_z0  [(size_t)BMAX * HDIM];
__device__ float d_z1  [(size_t)BMAX * 64];
__device__ int   d_count [NMAX];
__device__ int   d_rowptr[NMAX];
__device__ int   d_cursor[NMAX];
__device__ int   d_srcs  [EMAX];
__device__ int   d_bsum  [1024];

__device__ __forceinline__ float clamp10(float v) {
    return fminf(10.0f, fmaxf(-10.0f, v));
}

// ---- bf16 3-term split helpers ----
// hi = truncate-to-bf16 (top 8 mantissa bits, exact residual fits fp32),
// lo = rn-bf16 of residual. Error per product ~2^-16.
__device__ __forceinline__ void bf16pair(float x, float y, unsigned &hi, unsigned &lo) {
    unsigned ux = __float_as_uint(x), uy = __float_as_uint(y);
    hi = (uy & 0xffff0000u) | (ux >> 16);
    float lx = x - __uint_as_float(ux & 0xffff0000u);
    float ly = y - __uint_as_float(uy & 0xffff0000u);
    asm("cvt.rn.bf16x2.f32 %0, %1, %2;" : "=r"(lo) : "f"(ly), "f"(lx));
}

__device__ __forceinline__ void mma_bf16(float* c,
        unsigned a0, unsigned a1, unsigned a2, unsigned a3,
        unsigned b0, unsigned b1) {
    asm volatile(
        "mma.sync.aligned.m16n8k16.row.col.f32.bf16.bf16.f32 "
        "{%0,%1,%2,%3}, {%4,%5,%6,%7}, {%8,%9}, {%0,%1,%2,%3};"
        : "+f"(c[0]), "+f"(c[1]), "+f"(c[2]), "+f"(c[3])
        : "r"(a0), "r"(a1), "r"(a2), "r"(a3), "r"(b0), "r"(b1));
}

// ---------------- CSR build ----------------
__global__ void k_zero(int n) {
    int i = blockIdx.x * blockDim.x + threadIdx.x;
    if (i < n) { d_count[i] = 0; d_cursor[i] = 0; }
}

__global__ void k_count(const int* __restrict__ dst, int E) {
    int e = blockIdx.x * blockDim.x + threadIdx.x;
    if (e < E) atomicAdd(&d_count[dst[e]], 1);
}

__global__ void k_scan1(int n) {
    __shared__ int sh[1024];
    int i = blockIdx.x * 1024 + threadIdx.x;
    int v = (i < n) ? d_count[i] : 0;
    sh[threadIdx.x] = v;
    __syncthreads();
    for (int off = 1; off < 1024; off <<= 1) {
        int t = (threadIdx.x >= off) ? sh[threadIdx.x - off] : 0;
        __syncthreads();
        sh[threadIdx.x] += t;
        __syncthreads();
    }
    if (i < n) d_rowptr[i] = sh[threadIdx.x] - v;
    if (threadIdx.x == 1023) d_bsum[blockIdx.x] = sh[1023];
}

__global__ void k_scan2(int nb) {
    __shared__ int sh[1024];
    int v = (threadIdx.x < nb) ? d_bsum[threadIdx.x] : 0;
    sh[threadIdx.x] = v;
    __syncthreads();
    for (int off = 1; off < 1024; off <<= 1) {
        int t = (threadIdx.x >= off) ? sh[threadIdx.x - off] : 0;
        __syncthreads();
        sh[threadIdx.x] += t;
        __syncthreads();
    }
    if (threadIdx.x < nb) d_bsum[threadIdx.x] = sh[threadIdx.x] - v;
}

__global__ void k_scan3(int n) {
    int i = blockIdx.x * blockDim.x + threadIdx.x;
    if (i < n) d_rowptr[i] += d_bsum[i >> 10];
}

__global__ void k_scatter(const int* __restrict__ src, const int* __restrict__ dst, int E) {
    int e = blockIdx.x * blockDim.x + threadIdx.x;
    if (e < E) {
        int d = dst[e];
        int pos = atomicAdd(&d_cursor[d], 1);
        d_srcs[d_rowptr[d] + pos] = src[e];
    }
}

// ---------------- mean aggregation: one warp per row, 4-way MLP unroll ----------------
__global__ void k_agg(const float* __restrict__ X, const int* __restrict__ gath,
                      float* __restrict__ out, int nrows) {
    int w = (blockIdx.x * blockDim.x + threadIdx.x) >> 5;
    int lane = threadIdx.x & 31;
    if (w >= nrows) return;
    int node = gath ? gath[w] : w;
    int start = d_rowptr[node];
    int cnt   = d_count[node];
    const float* base = X + (lane << 2);
    float4 acc = make_float4(0.f, 0.f, 0.f, 0.f);
    int j = 0;
    for (; j + 3 < cnt; j += 4) {
        int s0 = d_srcs[start + j];
        int s1 = d_srcs[start + j + 1];
        int s2 = d_srcs[start + j + 2];
        int s3 = d_srcs[start + j + 3];
        float4 v0 = *reinterpret_cast<const float4*>(base + (size_t)s0 * 128);
        float4 v1 = *reinterpret_cast<const float4*>(base + (size_t)s1 * 128);
        float4 v2 = *reinterpret_cast<const float4*>(base + (size_t)s2 * 128);
        float4 v3 = *reinterpret_cast<const float4*>(base + (size_t)s3 * 128);
        acc.x += (v0.x + v1.x) + (v2.x + v3.x);
        acc.y += (v0.y + v1.y) + (v2.y + v3.y);
        acc.z += (v0.z + v1.z) + (v2.z + v3.z);
        acc.w += (v0.w + v1.w) + (v2.w + v3.w);
    }
    for (; j < cnt; j++) {
        int s0 = d_srcs[start + j];
        float4 v0 = *reinterpret_cast<const float4*>(base + (size_t)s0 * 128);
        acc.x += v0.x; acc.y += v0.y; acc.z += v0.z; acc.w += v0.w;
    }
    float inv = 1.0f / fmaxf((float)cnt, 1.0f);
    acc.x *= inv; acc.y *= inv; acc.z *= inv; acc.w *= inv;
    *reinterpret_cast<float4*>(out + (size_t)w * 128 + (lane << 2)) = acc;
}

// ---------------- fused 3x-bf16 tensor-core GEMM (m16n8k16) ----------------
// C[M,Nout] = act( [A0 | A1(gathered,clipped)] @ [W0 | W1]^T
//                  + bias1 + bias2 + roleW[:, roleOff + roles[row]] )
// Tile: BM=128, BN=64, BK=16. colBase = bx*64 (+colSkip for bx>=2).
// SMEM: hi/lo planes, 8 k-pair uints per row, stride 12 (bank-conflict-free).
__global__ __launch_bounds__(256, 2)
void k_mma(const float* __restrict__ A0, const float* __restrict__ A1,
           const int* __restrict__ g1, int clip1, int K0, int K1,
           const float* __restrict__ W0, int ldw0,
           const float* __restrict__ W1, int ldw1, int wvec,
           const float* __restrict__ bias1, const float* __restrict__ bias2,
           const float* __restrict__ roleW, int roleLd, int roleOff,
           const int* __restrict__ roles,
           float* __restrict__ C, int ldc, int M, int Nout, int act, int colSkip) {
    __shared__ unsigned Ah[128][12], Al[128][12];
    __shared__ unsigned Bh[64][12],  Bl[64][12];
    const int tid = threadIdx.x;
    const int lane = tid & 31;
    const int wid = tid >> 5;
    const int warp_m = wid & 3;   // 4 x 32 rows
    const int warp_n = wid >> 2;  // 2 x 32 cols
    const int rowBase = blockIdx.y * 128;
    int colBase = blockIdx.x * 64;
    if (blockIdx.x >= 2) colBase += colSkip;
    const int K = K0 + K1;
    const int ar = lane >> 2, ac = lane & 3;

    float acc[2][4][4];
#pragma unroll
    for (int i = 0; i < 2; i++)
#pragma unroll
        for (int j = 0; j < 4; j++)
#pragma unroll
            for (int k = 0; k < 4; k++) acc[i][j][k] = 0.f;

    for (int kt = 0; kt < K; kt += 16) {
        // ---- A tile: 128 rows x 16 k, 2 float4 per thread ----
#pragma unroll
        for (int it = 0; it < 2; it++) {
            int idx = tid + it * 256;        // 0..511
            int m = idx >> 2;                // 0..127
            int kq = (idx & 3) << 2;         // 0,4,8,12
            int row = rowBase + m;
            float4 v = make_float4(0.f, 0.f, 0.f, 0.f);
            if (row < M) {
                int kg = kt + kq;
                if (kg < K0) {
                    v = *reinterpret_cast<const float4*>(A0 + (size_t)row * K0 + kg);
                } else {
                    int r1 = g1 ? g1[row] : row;
                    v = *reinterpret_cast<const float4*>(A1 + (size_t)r1 * K1 + (kg - K0));
                    if (clip1) {
                        v.x = clamp10(v.x); v.y = clamp10(v.y);
                        v.z = clamp10(v.z); v.w = clamp10(v.w);
                    }
                }
            }
            unsigned h0, l0, h1, l1;
            bf16pair(v.x, v.y, h0, l0);
            bf16pair(v.z, v.w, h1, l1);
            int p = kq >> 1;                 // pair col: 0,2,4,6
            Ah[m][p] = h0; Ah[m][p + 1] = h1;
            Al[m][p] = l0; Al[m][p + 1] = l1;
        }
        // ---- B tile: 64 n x 16 k ----
        if (wvec) {
            int n = tid >> 2;                // 0..63
            int kq = (tid & 3) << 2;
            int ng = colBase + n;
            float4 v = make_float4(0.f, 0.f, 0.f, 0.f);
            if (ng < Nout) {
                int kg = kt + kq;
                v = (kg < K0) ? *reinterpret_cast<const float4*>(W0 + (size_t)ng * ldw0 + kg)
                              : *reinterpret_cast<const float4*>(W1 + (size_t)ng * ldw1 + (kg - K0));
            }
            unsigned h0, l0, h1, l1;
            bf16pair(v.x, v.y, h0, l0);
            bf16pair(v.z, v.w, h1, l1);
            int p = kq >> 1;
            Bh[n][p] = h0; Bh[n][p + 1] = h1;
            Bl[n][p] = l0; Bl[n][p + 1] = l1;
        } else {  // scalar path (w_ih row stride 261, unaligned)
#pragma unroll
            for (int it = 0; it < 2; it++) {
                int idx = tid + it * 256;    // 0..511
                int n = idx >> 3;            // 0..63
                int p = idx & 7;             // k-pair 0..7
                int ng = colBase + n;
                float w0 = 0.f, w1 = 0.f;
                if (ng < Nout) {
                    int kg = kt + p * 2;
                    if (kg < K0) {
                        const float* wp = W0 + (size_t)ng * ldw0 + kg;
                        w0 = wp[0]; w1 = wp[1];
                    } else {
                        const float* wp = W1 + (size_t)ng * ldw1 + (kg - K0);
                        w0 = wp[0]; w1 = wp[1];
                    }
                }
                unsigned h, l;
                bf16pair(w0, w1, h, l);
                Bh[n][p] = h; Bl[n][p] = l;
            }
        }
        __syncthreads();
        // ---- compute: one k16 step, 3 MMAs per (mt,nb) ----
        unsigned ah[2][4], al[2][4];
#pragma unroll
        for (int mt = 0; mt < 2; mt++) {
            int r = warp_m * 32 + mt * 16 + ar;
            ah[mt][0] = Ah[r    ][ac];     al[mt][0] = Al[r    ][ac];
            ah[mt][1] = Ah[r + 8][ac];     al[mt][1] = Al[r + 8][ac];
            ah[mt][2] = Ah[r    ][ac + 4]; al[mt][2] = Al[r    ][ac + 4];
            ah[mt][3] = Ah[r + 8][ac + 4]; al[mt][3] = Al[r + 8][ac + 4];
        }
#pragma unroll
        for (int nb = 0; nb < 4; nb++) {
            int cn = warp_n * 32 + nb * 8 + ar;
            unsigned bh0 = Bh[cn][ac], bh1 = Bh[cn][ac + 4];
            unsigned bl0 = Bl[cn][ac], bl1 = Bl[cn][ac + 4];
#pragma unroll
            for (int mt = 0; mt < 2; mt++) {
                mma_bf16(acc[mt][nb], al[mt][0], al[mt][1], al[mt][2], al[mt][3], bh0, bh1); // lo*hi
                mma_bf16(acc[mt][nb], ah[mt][0], ah[mt][1], ah[mt][2], ah[mt][3], bl0, bl1); // hi*lo
                mma_bf16(acc[mt][nb], ah[mt][0], ah[mt][1], ah[mt][2], ah[mt][3], bh0, bh1); // hi*hi
            }
        }
        __syncthreads();
    }

    // ---- epilogue ----
#pragma unroll
    for (int mt = 0; mt < 2; mt++) {
        int r0 = rowBase + warp_m * 32 + mt * 16 + ar;
        int r1 = r0 + 8;
        int rl0 = 0, rl1 = 0;
        if (roleW) {
            if (r0 < M) rl0 = roles[r0];
            if (r1 < M) rl1 = roles[r1];
        }
#pragma unroll
        for (int nb = 0; nb < 4; nb++) {
            int c0 = colBase + warp_n * 32 + nb * 8 + ac * 2;
            if (c0 >= Nout) continue;
            float bs0 = 0.f, bs1 = 0.f;
            if (bias1) { bs0 += bias1[c0]; bs1 += bias1[c0 + 1]; }
            if (bias2) { bs0 += bias2[c0]; bs1 += bias2[c0 + 1]; }
            if (r0 < M) {
                float v0 = acc[mt][nb][0] + bs0;
                float v1 = acc[mt][nb][1] + bs1;
                if (roleW) {
                    v0 += roleW[(size_t)c0 * roleLd + roleOff + rl0];
                    v1 += roleW[(size_t)(c0 + 1) * roleLd + roleOff + rl0];
                }
                if (act == 1) { v0 = fmaxf(v0, 0.f); v1 = fmaxf(v1, 0.f); }
                else if (act == 2) { v0 = clamp10(v0); v1 = clamp10(v1); }
                *reinterpret_cast<float2*>(C + (size_t)r0 * ldc + c0) = make_float2(v0, v1);
            }
            if (r1 < M) {
                float v0 = acc[mt][nb][2] + bs0;
                float v1 = acc[mt][nb][3] + bs1;
                if (roleW) {
                    v0 += roleW[(size_t)c0 * roleLd + roleOff + rl1];
                    v1 += roleW[(size_t)(c0 + 1) * roleLd + roleOff + rl1];
                }
                if (act == 1) { v0 = fmaxf(v0, 0.f); v1 = fmaxf(v1, 0.f); }
                else if (act == 2) { v0 = clamp10(v0); v1 = clamp10(v1); }
                *reinterpret_cast<float2*>(C + (size_t)r1 * ldc + c0) = make_float2(v0, v1);
            }
        }
    }
}

// ---------------- LSTM pointwise (f-gate dead: c0=0) ----------------
__global__ void k_lstm(int B) {
    int idx = blockIdx.x * blockDim.x + threadIdx.x;
    if (idx >= B * 128) return;
    int b = idx >> 7, j = idx & 127;
    const float* g = d_gate + (size_t)b * 512;
    float i_ = g[j];
    float gg = g[256 + j];
    float o_ = g[384 + j];
    float si = 1.0f / (1.0f + __expf(-i_));
    float so = 1.0f / (1.0f + __expf(-o_));
    float c = si * tanhf(gg);
    d_lstm[idx] = clamp10(so * tanhf(c));
}

// ---------------- final tiny layer: out[B,5] = z1 @ wc2^T + bc2 ----------------
__global__ void k_out(const float* __restrict__ wc2, const float* __restrict__ bc2,
                      float* __restrict__ out, int B) {
    __shared__ float w[320];
    __shared__ float bb[5];
    int tid = threadIdx.x;
    if (tid < 320) w[tid] = wc2[tid];
    if (tid < 5)   bb[tid] = bc2[tid];
    __syncthreads();
    int b = blockIdx.x * blockDim.x + tid;
    if (b >= B) return;
    const float* z = d_z1 + (size_t)b * 64;
    float a0 = bb[0], a1 = bb[1], a2 = bb[2], a3 = bb[3], a4 = bb[4];
#pragma unroll
    for (int k = 0; k < 64; k++) {
        float zv = z[k];
        a0 += zv * w[k];
        a1 += zv * w[64 + k];
        a2 += zv * w[128 + k];
        a3 += zv * w[192 + k];
        a4 += zv * w[256 + k];
    }
    float* o = out + (size_t)b * 5;
    o[0] = a0; o[1] = a1; o[2] = a2; o[3] = a3; o[4] = a4;
}

// ---------------- launch ----------------
extern "C" void kernel_launch(void* const* d_in, const int* in_sizes, int n_in,
                              void* d_out, int out_size) {
    const float* x     = (const float*)d_in[0];
    const int*   edge  = (const int*)  d_in[1];
    const int*   uid   = (const int*)  d_in[2];
    const int*   roles = (const int*)  d_in[3];
    const float* w_l0  = (const float*)d_in[4];
    const float* b_l0  = (const float*)d_in[5];
    const float* w_r0  = (const float*)d_in[6];
    const float* w_l1  = (const float*)d_in[7];
    const float* b_l1  = (const float*)d_in[8];
    const float* w_r1  = (const float*)d_in[9];
    const float* w_ih  = (const float*)d_in[10];
    /* w_hh unused: h0 = 0 */
    const float* b_ih  = (const float*)d_in[12];
    const float* b_hh  = (const float*)d_in[13];
    const float* wc0   = (const float*)d_in[14];
    const float* bc0   = (const float*)d_in[15];
    const float* wc1   = (const float*)d_in[16];
    const float* bc1   = (const float*)d_in[17];
    const float* wc2   = (const float*)d_in[18];
    const float* bc2   = (const float*)d_in[19];
    float* out = (float*)d_out;

    const int N = in_sizes[0] / FDIM;
    const int E = in_sizes[1] / 2;
    const int B = in_sizes[2];
    const int* src = edge;
    const int* dst = edge + E;

    float *mean0, *hbuf, *aggU, *ue, *gate, *lstm, *z0, *z1;
    cudaGetSymbolAddress((void**)&mean0, d_mean0);
    cudaGetSymbolAddress((void**)&hbuf,  d_h);
    cudaGetSymbolAddress((void**)&aggU,  d_aggU);
    cudaGetSymbolAddress((void**)&ue,    d_ue);
    cudaGetSymbolAddress((void**)&gate,  d_gate);
    cudaGetSymbolAddress((void**)&lstm,  d_lstm);
    cudaGetSymbolAddress((void**)&z0,    d_z0);
    cudaGetSymbolAddress((void**)&z1,    d_z1);

    // --- CSR build ---
    k_zero<<<(N + 255) / 256, 256>>>(N);
    k_count<<<(E + 255) / 256, 256>>>(dst, E);
    int nb = (N + 1023) / 1024;
    k_scan1<<<nb, 1024>>>(N);
    k_scan2<<<1, 1024>>>(nb);
    k_scan3<<<(N + 255) / 256, 256>>>(N);
    k_scatter<<<(E + 255) / 256, 256>>>(src, dst, E);

    // --- layer 0 ---
    k_agg<<<(N + 7) / 8, 256>>>(x, nullptr, mean0, N);
    k_mma<<<dim3(2, (N + 127) / 128), 256>>>(
        mean0, x, nullptr, 0, 128, 128,
        w_l0, 128, w_r0, 128, /*wvec*/1,
        b_l0, nullptr, nullptr, 0, 0, nullptr,
        hbuf, 128, N, 128, /*relu*/1, 0);

    // --- layer 1 (user rows only) ---
    k_agg<<<(B + 7) / 8, 256>>>(hbuf, uid, aggU, B);
    k_mma<<<dim3(2, (B + 127) / 128), 256>>>(
        aggU, hbuf, uid, 0, 128, 128,
        w_l1, 128, w_r1, 128, 1,
        b_l1, nullptr, nullptr, 0, 0, nullptr,
        ue, 128, B, 128, /*clip*/2, 0);

    // --- gates (skip dead f-gate columns 128..255): blocks cover {0,64,256,320,384,448} ---
    k_mma<<<dim3(6, (B + 127) / 128), 256>>>(
        ue, x, uid, /*clip uf*/1, 128, 128,
        w_ih, 261, w_ih + 128, 261, /*wvec*/0,
        b_ih, b_hh, w_ih, 261, 256, roles,
        gate, 512, B, 512, /*none*/0, /*colSkip*/128);
    k_lstm<<<(B * 128 + 255) / 256, 256>>>(B);

    // --- classifier head ---
    k_mma<<<dim3(2, (B + 127) / 128), 256>>>(
        ue, lstm, nullptr, 0, 128, 128,
        wc0, 256, wc0 + 128, 256, 1,
        bc0, nullptr, nullptr, 0, 0, nullptr,
        z0, 128, B, 128, 1, 0);
    k_mma<<<dim3(1, (B + 127) / 128), 256>>>(
        z0, nullptr, nullptr, 0, 128, 0,
        wc1, 128, nullptr, 0, 1,
        bc1, nullptr, nullptr, 0, 0, nullptr,
        z1, 64, B, 64, 1, 0);
    k_out<<<(B + 511) / 512, 512>>>(wc2, bc2, out, B);
}

// round 8
// speedup vs baseline: 2.2669x; 1.1806x over previous
#include <cuda_runtime.h>
#include <cuda_bf16.h>
#include <math.h>
#include <stdint.h>

// ---------------- capacities ----------------
#define NMAX 100096
#define EMAX 1600000
#define BMAX 16384
#define FDIM 128
#define HDIM 128

// ---------------- device scratch ----------------
__device__ float d_mean0[(size_t)NMAX * FDIM];
__device__ float d_h   [(size_t)NMAX * HDIM];
__device__ float d_aggU[(size_t)BMAX * HDIM];
__device__ float d_ue  [(size_t)BMAX * HDIM];
__device__ float d_gate[(size_t)BMAX * 512];
__device__ float d_lstm[(size_t)BMAX * HDIM];
__device__ float d_z0  [(size_t)BMAX * HDIM];
__device__ float d_z1  [(size_t)BMAX * 64];
__device__ int   d_count [NMAX];
__device__ int   d_rowptr[NMAX];
__device__ int   d_cursor[NMAX];
__device__ int   d_srcs  [EMAX];
__device__ int   d_bsum  [1024];

__device__ __forceinline__ float clamp10(float v) {
    return fminf(10.0f, fmaxf(-10.0f, v));
}

// ---- bf16 3-term split helpers ----
// hi = truncate-to-bf16, lo = rn-bf16 of exact residual. Per-product err ~2^-16.
__device__ __forceinline__ void bf16pair(float x, float y, unsigned &hi, unsigned &lo) {
    unsigned ux = __float_as_uint(x), uy = __float_as_uint(y);
    hi = (uy & 0xffff0000u) | (ux >> 16);
    float lx = x - __uint_as_float(ux & 0xffff0000u);
    float ly = y - __uint_as_float(uy & 0xffff0000u);
    asm("cvt.rn.bf16x2.f32 %0, %1, %2;" : "=r"(lo) : "f"(ly), "f"(lx));
}

__device__ __forceinline__ void mma_bf16(float* c,
        unsigned a0, unsigned a1, unsigned a2, unsigned a3,
        unsigned b0, unsigned b1) {
    asm volatile(
        "mma.sync.aligned.m16n8k16.row.col.f32.bf16.bf16.f32 "
        "{%0,%1,%2,%3}, {%4,%5,%6,%7}, {%8,%9}, {%0,%1,%2,%3};"
        : "+f"(c[0]), "+f"(c[1]), "+f"(c[2]), "+f"(c[3])
        : "r"(a0), "r"(a1), "r"(a2), "r"(a3), "r"(b0), "r"(b1));
}

// ---------------- CSR build ----------------
__global__ void k_zero(int n) {
    int i = blockIdx.x * blockDim.x + threadIdx.x;
    if (i < n) { d_count[i] = 0; d_cursor[i] = 0; }
}

__global__ void k_count(const int* __restrict__ dst, int E) {
    int e = blockIdx.x * blockDim.x + threadIdx.x;
    if (e < E) atomicAdd(&d_count[dst[e]], 1);
}

__global__ void k_scan1(int n) {
    __shared__ int sh[1024];
    int i = blockIdx.x * 1024 + threadIdx.x;
    int v = (i < n) ? d_count[i] : 0;
    sh[threadIdx.x] = v;
    __syncthreads();
    for (int off = 1; off < 1024; off <<= 1) {
        int t = (threadIdx.x >= off) ? sh[threadIdx.x - off] : 0;
        __syncthreads();
        sh[threadIdx.x] += t;
        __syncthreads();
    }
    if (i < n) d_rowptr[i] = sh[threadIdx.x] - v;
    if (threadIdx.x == 1023) d_bsum[blockIdx.x] = sh[1023];
}

__global__ void k_scan2(int nb) {
    __shared__ int sh[1024];
    int v = (threadIdx.x < nb) ? d_bsum[threadIdx.x] : 0;
    sh[threadIdx.x] = v;
    __syncthreads();
    for (int off = 1; off < 1024; off <<= 1) {
        int t = (threadIdx.x >= off) ? sh[threadIdx.x - off] : 0;
        __syncthreads();
        sh[threadIdx.x] += t;
        __syncthreads();
    }
    if (threadIdx.x < nb) d_bsum[threadIdx.x] = sh[threadIdx.x] - v;
}

__global__ void k_scan3(int n) {
    int i = blockIdx.x * blockDim.x + threadIdx.x;
    if (i < n) d_rowptr[i] += d_bsum[i >> 10];
}

__global__ void k_scatter(const int* __restrict__ src, const int* __restrict__ dst, int E) {
    int e = blockIdx.x * blockDim.x + threadIdx.x;
    if (e < E) {
        int d = dst[e];
        int pos = atomicAdd(&d_cursor[d], 1);
        d_srcs[d_rowptr[d] + pos] = src[e];
    }
}

// ---------------- mean aggregation: one warp per row, 4-way MLP unroll ----------------
__global__ void k_agg(const float* __restrict__ X, const int* __restrict__ gath,
                      float* __restrict__ out, int nrows) {
    int w = (blockIdx.x * blockDim.x + threadIdx.x) >> 5;
    int lane = threadIdx.x & 31;
    if (w >= nrows) return;
    int node = gath ? gath[w] : w;
    int start = d_rowptr[node];
    int cnt   = d_count[node];
    const float* base = X + (lane << 2);
    float4 acc = make_float4(0.f, 0.f, 0.f, 0.f);
    int j = 0;
    for (; j + 3 < cnt; j += 4) {
        int s0 = d_srcs[start + j];
        int s1 = d_srcs[start + j + 1];
        int s2 = d_srcs[start + j + 2];
        int s3 = d_srcs[start + j + 3];
        float4 v0 = *reinterpret_cast<const float4*>(base + (size_t)s0 * 128);
        float4 v1 = *reinterpret_cast<const float4*>(base + (size_t)s1 * 128);
        float4 v2 = *reinterpret_cast<const float4*>(base + (size_t)s2 * 128);
        float4 v3 = *reinterpret_cast<const float4*>(base + (size_t)s3 * 128);
        acc.x += (v0.x + v1.x) + (v2.x + v3.x);
        acc.y += (v0.y + v1.y) + (v2.y + v3.y);
        acc.z += (v0.z + v1.z) + (v2.z + v3.z);
        acc.w += (v0.w + v1.w) + (v2.w + v3.w);
    }
    for (; j < cnt; j++) {
        int s0 = d_srcs[start + j];
        float4 v0 = *reinterpret_cast<const float4*>(base + (size_t)s0 * 128);
        acc.x += v0.x; acc.y += v0.y; acc.z += v0.z; acc.w += v0.w;
    }
    float inv = 1.0f / fmaxf((float)cnt, 1.0f);
    acc.x *= inv; acc.y *= inv; acc.z *= inv; acc.w *= inv;
    *reinterpret_cast<float4*>(out + (size_t)w * 128 + (lane << 2)) = acc;
}

// ---------------- fused 3x-bf16 tensor-core GEMM, double-buffered pipeline ----------------
// C[M,Nout] = act( [A0 | A1(gathered,clipped)] @ [W0 | W1]^T
//                  + bias1 + bias2 + roleW[:, roleOff + roles[row]] )
// Tile: BM=128, BN=64, BK=16; 1 __syncthreads per k-step; global loads of step s+1
// issued before compute of step s (register prefetch into alternate SMEM buffer).
__global__ __launch_bounds__(256, 2)
void k_mma(const float* __restrict__ A0, const float* __restrict__ A1,
           const int* __restrict__ g1, int clip1, int K0, int K1,
           const float* __restrict__ W0, int ldw0,
           const float* __restrict__ W1, int ldw1, int wvec,
           const float* __restrict__ bias1, const float* __restrict__ bias2,
           const float* __restrict__ roleW, int roleLd, int roleOff,
           const int* __restrict__ roles,
           float* __restrict__ C, int ldc, int M, int Nout, int act, int colSkip) {
    __shared__ unsigned Ah[2][128][12], Al[2][128][12];
    __shared__ unsigned Bh[2][64][12],  Bl[2][64][12];
    const int tid = threadIdx.x;
    const int lane = tid & 31;
    const int wid = tid >> 5;
    const int warp_m = wid & 3;   // 4 x 32 rows
    const int warp_n = wid >> 2;  // 2 x 32 cols
    const int rowBase = blockIdx.y * 128;
    int colBase = blockIdx.x * 64;
    if (blockIdx.x >= 2) colBase += colSkip;
    const int K = K0 + K1;
    const int nsteps = K >> 4;
    const int ar = lane >> 2, ac = lane & 3;

    // per-thread A-load coords: 2 chunks, each (m, kq)
    const int am0 = tid >> 2,             akq0 = (tid & 3) << 2;
    const int am1 = (tid + 256) >> 2,     akq1 = akq0;          // same kq pattern
    // B vec-load coords
    const int bn = tid >> 2,              bkq = (tid & 3) << 2;

    float acc[2][4][4];
#pragma unroll
    for (int i = 0; i < 2; i++)
#pragma unroll
        for (int j = 0; j < 4; j++)
#pragma unroll
            for (int k = 0; k < 4; k++) acc[i][j][k] = 0.f;

    float4 va[2];
    float4 vb;
    float  wb[2][2];

    // ---- loaders (global -> regs) ----
    auto loadA = [&](int kt) {
#pragma unroll
        for (int it = 0; it < 2; it++) {
            int m  = it ? am1 : am0;
            int kq = it ? akq1 : akq0;
            int row = rowBase + m;
            float4 v = make_float4(0.f, 0.f, 0.f, 0.f);
            if (row < M) {
                int kg = kt + kq;
                if (kg < K0) {
                    v = *reinterpret_cast<const float4*>(A0 + (size_t)row * K0 + kg);
                } else {
                    int r1 = g1 ? g1[row] : row;
                    v = *reinterpret_cast<const float4*>(A1 + (size_t)r1 * K1 + (kg - K0));
                    if (clip1) {
                        v.x = clamp10(v.x); v.y = clamp10(v.y);
                        v.z = clamp10(v.z); v.w = clamp10(v.w);
                    }
                }
            }
            va[it] = v;
        }
    };
    auto loadB = [&](int kt) {
        if (wvec) {
            int ng = colBase + bn;
            float4 v = make_float4(0.f, 0.f, 0.f, 0.f);
            if (ng < Nout) {
                int kg = kt + bkq;
                v = (kg < K0) ? *reinterpret_cast<const float4*>(W0 + (size_t)ng * ldw0 + kg)
                              : *reinterpret_cast<const float4*>(W1 + (size_t)ng * ldw1 + (kg - K0));
            }
            vb = v;
        } else {
#pragma unroll
            for (int it = 0; it < 2; it++) {
                int idx = tid + it * 256;
                int n = idx >> 3;
                int p = idx & 7;
                int ng = colBase + n;
                float w0 = 0.f, w1 = 0.f;
                if (ng < Nout) {
                    int kg = kt + p * 2;
                    if (kg < K0) {
                        const float* wp = W0 + (size_t)ng * ldw0 + kg;
                        w0 = wp[0]; w1 = wp[1];
                    } else {
                        const float* wp = W1 + (size_t)ng * ldw1 + (kg - K0);
                        w0 = wp[0]; w1 = wp[1];
                    }
                }
                wb[it][0] = w0; wb[it][1] = w1;
            }
        }
    };
    // ---- converters (regs -> smem[buf]) ----
    auto storeA = [&](int buf) {
#pragma unroll
        for (int it = 0; it < 2; it++) {
            int m  = it ? am1 : am0;
            int kq = it ? akq1 : akq0;
            unsigned h0, l0, h1, l1;
            bf16pair(va[it].x, va[it].y, h0, l0);
            bf16pair(va[it].z, va[it].w, h1, l1);
            int p = kq >> 1;
            Ah[buf][m][p] = h0; Ah[buf][m][p + 1] = h1;
            Al[buf][m][p] = l0; Al[buf][m][p + 1] = l1;
        }
    };
    auto storeB = [&](int buf) {
        if (wvec) {
            unsigned h0, l0, h1, l1;
            bf16pair(vb.x, vb.y, h0, l0);
            bf16pair(vb.z, vb.w, h1, l1);
            int p = bkq >> 1;
            Bh[buf][bn][p] = h0; Bh[buf][bn][p + 1] = h1;
            Bl[buf][bn][p] = l0; Bl[buf][bn][p + 1] = l1;
        } else {
#pragma unroll
            for (int it = 0; it < 2; it++) {
                int idx = tid + it * 256;
                int n = idx >> 3;
                int p = idx & 7;
                unsigned h, l;
                bf16pair(wb[it][0], wb[it][1], h, l);
                Bh[buf][n][p] = h; Bl[buf][n][p] = l;
            }
        }
    };

    // ---- prologue: tile 0 ----
    loadA(0); loadB(0);
    storeA(0); storeB(0);
    __syncthreads();

    for (int s = 0; s < nsteps; s++) {
        int buf = s & 1;
        if (s + 1 < nsteps) { loadA((s + 1) << 4); loadB((s + 1) << 4); }

        // ---- compute on smem[buf]: 24 MMAs ----
        unsigned ah[2][4], al[2][4];
#pragma unroll
        for (int mt = 0; mt < 2; mt++) {
            int r = warp_m * 32 + mt * 16 + ar;
            ah[mt][0] = Ah[buf][r    ][ac];     al[mt][0] = Al[buf][r    ][ac];
            ah[mt][1] = Ah[buf][r + 8][ac];     al[mt][1] = Al[buf][r + 8][ac];
            ah[mt][2] = Ah[buf][r    ][ac + 4]; al[mt][2] = Al[buf][r    ][ac + 4];
            ah[mt][3] = Ah[buf][r + 8][ac + 4]; al[mt][3] = Al[buf][r + 8][ac + 4];
        }
#pragma unroll
        for (int nb = 0; nb < 4; nb++) {
            int cn = warp_n * 32 + nb * 8 + ar;
            unsigned bh0 = Bh[buf][cn][ac], bh1 = Bh[buf][cn][ac + 4];
            unsigned bl0 = Bl[buf][cn][ac], bl1 = Bl[buf][cn][ac + 4];
#pragma unroll
            for (int mt = 0; mt < 2; mt++) {
                mma_bf16(acc[mt][nb], al[mt][0], al[mt][1], al[mt][2], al[mt][3], bh0, bh1); // lo*hi
                mma_bf16(acc[mt][nb], ah[mt][0], ah[mt][1], ah[mt][2], ah[mt][3], bl0, bl1); // hi*lo
                mma_bf16(acc[mt][nb], ah[mt][0], ah[mt][1], ah[mt][2], ah[mt][3], bh0, bh1); // hi*hi
            }
        }

        if (s + 1 < nsteps) { storeA(buf ^ 1); storeB(buf ^ 1); }
        __syncthreads();
    }

    // ---- epilogue ----
#pragma unroll
    for (int mt = 0; mt < 2; mt++) {
        int r0 = rowBase + warp_m * 32 + mt * 16 + ar;
        int r1 = r0 + 8;
        int rl0 = 0, rl1 = 0;
        if (roleW) {
            if (r0 < M) rl0 = roles[r0];
            if (r1 < M) rl1 = roles[r1];
        }
#pragma unroll
        for (int nb = 0; nb < 4; nb++) {
            int c0 = colBase + warp_n * 32 + nb * 8 + ac * 2;
            if (c0 >= Nout) continue;
            float bs0 = 0.f, bs1 = 0.f;
            if (bias1) { bs0 += bias1[c0]; bs1 += bias1[c0 + 1]; }
            if (bias2) { bs0 += bias2[c0]; bs1 += bias2[c0 + 1]; }
            if (r0 < M) {
                float v0 = acc[mt][nb][0] + bs0;
                float v1 = acc[mt][nb][1] + bs1;
                if (roleW) {
                    v0 += roleW[(size_t)c0 * roleLd + roleOff + rl0];
                    v1 += roleW[(size_t)(c0 + 1) * roleLd + roleOff + rl0];
                }
                if (act == 1) { v0 = fmaxf(v0, 0.f); v1 = fmaxf(v1, 0.f); }
                else if (act == 2) { v0 = clamp10(v0); v1 = clamp10(v1); }
                *reinterpret_cast<float2*>(C + (size_t)r0 * ldc + c0) = make_float2(v0, v1);
            }
            if (r1 < M) {
                float v0 = acc[mt][nb][2] + bs0;
                float v1 = acc[mt][nb][3] + bs1;
                if (roleW) {
                    v0 += roleW[(size_t)c0 * roleLd + roleOff + rl1];
                    v1 += roleW[(size_t)(c0 + 1) * roleLd + roleOff + rl1];
                }
                if (act == 1) { v0 = fmaxf(v0, 0.f); v1 = fmaxf(v1, 0.f); }
                else if (act == 2) { v0 = clamp10(v0); v1 = clamp10(v1); }
                *reinterpret_cast<float2*>(C + (size_t)r1 * ldc + c0) = make_float2(v0, v1);
            }
        }
    }
}

// ---------------- LSTM pointwise (f-gate dead: c0=0) ----------------
__global__ void k_lstm(int B) {
    int idx = blockIdx.x * blockDim.x + threadIdx.x;
    if (idx >= B * 128) return;
    int b = idx >> 7, j = idx & 127;
    const float* g = d_gate + (size_t)b * 512;
    float i_ = g[j];
    float gg = g[256 + j];
    float o_ = g[384 + j];
    float si = 1.0f / (1.0f + __expf(-i_));
    float so = 1.0f / (1.0f + __expf(-o_));
    float c = si * tanhf(gg);
    d_lstm[idx] = clamp10(so * tanhf(c));
}

// ---------------- final tiny layer: out[B,5] = z1 @ wc2^T + bc2 ----------------
__global__ void k_out(const float* __restrict__ wc2, const float* __restrict__ bc2,
                      float* __restrict__ out, int B) {
    __shared__ float w[320];
    __shared__ float bb[5];
    int tid = threadIdx.x;
    if (tid < 320) w[tid] = wc2[tid];
    if (tid < 5)   bb[tid] = bc2[tid];
    __syncthreads();
    int b = blockIdx.x * blockDim.x + tid;
    if (b >= B) return;
    const float* z = d_z1 + (size_t)b * 64;
    float a0 = bb[0], a1 = bb[1], a2 = bb[2], a3 = bb[3], a4 = bb[4];
#pragma unroll
    for (int k = 0; k < 64; k++) {
        float zv = z[k];
        a0 += zv * w[k];
        a1 += zv * w[64 + k];
        a2 += zv * w[128 + k];
        a3 += zv * w[192 + k];
        a4 += zv * w[256 + k];
    }
    float* o = out + (size_t)b * 5;
    o[0] = a0; o[1] = a1; o[2] = a2; o[3] = a3; o[4] = a4;
}

// ---------------- launch ----------------
extern "C" void kernel_launch(void* const* d_in, const int* in_sizes, int n_in,
                              void* d_out, int out_size) {
    const float* x     = (const float*)d_in[0];
    const int*   edge  = (const int*)  d_in[1];
    const int*   uid   = (const int*)  d_in[2];
    const int*   roles = (const int*)  d_in[3];
    const float* w_l0  = (const float*)d_in[4];
    const float* b_l0  = (const float*)d_in[5];
    const float* w_r0  = (const float*)d_in[6];
    const float* w_l1  = (const float*)d_in[7];
    const float* b_l1  = (const float*)d_in[8];
    const float* w_r1  = (const float*)d_in[9];
    const float* w_ih  = (const float*)d_in[10];
    /* w_hh unused: h0 = 0 */
    const float* b_ih  = (const float*)d_in[12];
    const float* b_hh  = (const float*)d_in[13];
    const float* wc0   = (const float*)d_in[14];
    const float* bc0   = (const float*)d_in[15];
    const float* wc1   = (const float*)d_in[16];
    const float* bc1   = (const float*)d_in[17];
    const float* wc2   = (const float*)d_in[18];
    const float* bc2   = (const float*)d_in[19];
    float* out = (float*)d_out;

    const int N = in_sizes[0] / FDIM;
    const int E = in_sizes[1] / 2;
    const int B = in_sizes[2];
    const int* src = edge;
    const int* dst = edge + E;

    float *mean0, *hbuf, *aggU, *ue, *gate, *lstm, *z0, *z1;
    cudaGetSymbolAddress((void**)&mean0, d_mean0);
    cudaGetSymbolAddress((void**)&hbuf,  d_h);
    cudaGetSymbolAddress((void**)&aggU,  d_aggU);
    cudaGetSymbolAddress((void**)&ue,    d_ue);
    cudaGetSymbolAddress((void**)&gate,  d_gate);
    cudaGetSymbolAddress((void**)&lstm,  d_lstm);
    cudaGetSymbolAddress((void**)&z0,    d_z0);
    cudaGetSymbolAddress((void**)&z1,    d_z1);

    // --- CSR build ---
    k_zero<<<(N + 255) / 256, 256>>>(N);
    k_count<<<(E + 255) / 256, 256>>>(dst, E);
    int nb = (N + 1023) / 1024;
    k_scan1<<<nb, 1024>>>(N);
    k_scan2<<<1, 1024>>>(nb);
    k_scan3<<<(N + 255) / 256, 256>>>(N);
    k_scatter<<<(E + 255) / 256, 256>>>(src, dst, E);

    // --- layer 0 ---
    k_agg<<<(N + 7) / 8, 256>>>(x, nullptr, mean0, N);
    k_mma<<<dim3(2, (N + 127) / 128), 256>>>(
        mean0, x, nullptr, 0, 128, 128,
        w_l0, 128, w_r0, 128, /*wvec*/1,
        b_l0, nullptr, nullptr, 0, 0, nullptr,
        hbuf, 128, N, 128, /*relu*/1, 0);

    // --- layer 1 (user rows only) ---
    k_agg<<<(B + 7) / 8, 256>>>(hbuf, uid, aggU, B);
    k_mma<<<dim3(2, (B + 127) / 128), 256>>>(
        aggU, hbuf, uid, 0, 128, 128,
        w_l1, 128, w_r1, 128, 1,
        b_l1, nullptr, nullptr, 0, 0, nullptr,
        ue, 128, B, 128, /*clip*/2, 0);

    // --- gates (skip dead f-gate columns 128..255): blocks cover {0,64,256,320,384,448} ---
    k_mma<<<dim3(6, (B + 127) / 128), 256>>>(
        ue, x, uid, /*clip uf*/1, 128, 128,
        w_ih, 261, w_ih + 128, 261, /*wvec*/0,
        b_ih, b_hh, w_ih, 261, 256, roles,
        gate, 512, B, 512, /*none*/0, /*colSkip*/128);
    k_lstm<<<(B * 128 + 255) / 256, 256>>>(B);

    // --- classifier head ---
    k_mma<<<dim3(2, (B + 127) / 128), 256>>>(
        ue, lstm, nullptr, 0, 128, 128,
        wc0, 256, wc0 + 128, 256, 1,
        bc0, nullptr, nullptr, 0, 0, nullptr,
        z0, 128, B, 128, 1, 0);
    k_mma<<<dim3(1, (B + 127) / 128), 256>>>(
        z0, nullptr, nullptr, 0, 128, 0,
        wc1, 128, nullptr, 0, 1,
        bc1, nullptr, nullptr, 0, 0, nullptr,
        z1, 64, B, 64, 1, 0);
    k_out<<<(B + 511) / 512, 512>>>(wc2, bc2, out, B);
}